// round 5
// baseline (speedup 1.0000x reference)
#include <cuda_runtime.h>
#include <math.h>

#define BB 64
#define LL 128
#define HID 768
#define CDIM 256
#define SDIM 64
#define NOUT (CDIM + SDIM)      // 320
#define FEAT 321
#define NIT 30
#define EPSV 0.05f
#define L2E 1.4426950408889634f
#define INFN 3.0e38f

// ---------------- device scratch ---------------------------------------------
__device__ float g_Cs[BB * LL * LL];   // scaled cost (only [0,n)^2 valid)
__device__ float g_sq[BB * LL];
__device__ float g_rep[BB * 2 * HID];
__device__ float g_fused[BB * NOUT];
__device__ float g_sink[3 * BB];
__device__ int   g_n0[BB], g_n1[BB];

// ---------------- K_sq: row squared norms ------------------------------------
__global__ void k_sq(const float* __restrict__ H) {
    int warp = (blockIdx.x * blockDim.x + threadIdx.x) >> 5;
    int lane = threadIdx.x & 31;
    if (warp >= BB * LL) return;
    const float4* p = (const float4*)(H + (size_t)warp * HID);
    float s = 0.f;
#pragma unroll
    for (int t = 0; t < HID / 128; t++) {
        float4 v = p[lane + 32 * t];
        s += v.x * v.x + v.y * v.y + v.z * v.z + v.w * v.w;
    }
#pragma unroll
    for (int o = 16; o; o >>= 1) s += __shfl_down_sync(0xffffffffu, s, o);
    if (lane == 0) g_sq[warp] = s;
}

// ---------------- K_rep: counts + masked means + cls -> g_rep -----------------
__global__ void k_rep(const float* __restrict__ H, const int* __restrict__ tt,
                      const int* __restrict__ am) {
    int b = blockIdx.x;
    int tid = threadIdx.x;                 // 128
    int d = blockIdx.y * 128 + tid;        // 0..767
    __shared__ float s_m0[LL], s_m1[LL];
    int a = am[b * LL + tid], t = tt[b * LL + tid];
    int f0 = (a == 1 && t == 0) ? 1 : 0;
    int f1 = (a == 1 && t == 1) ? 1 : 0;
    s_m0[tid] = (float)f0;
    s_m1[tid] = (float)f1;
    int n0 = __syncthreads_count(f0);
    int n1 = __syncthreads_count(f1);
    if (blockIdx.y == 0 && tid == 0) { g_n0[b] = n0; g_n1[b] = n1; }
    const float* Hb = H + (size_t)b * LL * HID;
    float a0 = 0.f, a1 = 0.f;
#pragma unroll 8
    for (int l = 0; l < LL; l++) {
        float h = Hb[l * HID + d];
        a0 += h * s_m0[l];
        a1 += h * s_m1[l];
    }
    float i0 = 1.f / fmaxf((float)n0, 1.f);
    float i1 = 1.f / fmaxf((float)n1, 1.f);
    g_rep[b * 2 * HID + d] = Hb[d];
    g_rep[b * 2 * HID + HID + d] = a0 * i0 - a1 * i1;
}

// ---------------- K_fused: 8 outputs x 4 batches per block --------------------
#define FB 4
__global__ void __launch_bounds__(256) k_fused(
        const float* __restrict__ Wc, const float* __restrict__ bc,
        const float* __restrict__ Ws, const float* __restrict__ bs,
        const float* __restrict__ gate) {
    int b0 = blockIdx.y * FB;
    int w = threadIdx.x >> 5, lane = threadIdx.x & 31;
    int o = blockIdx.x * 8 + w;   // 0..319
    __shared__ __align__(16) float s_rep[FB][2 * HID];
    {
        const float4* g4 = (const float4*)(g_rep + (size_t)b0 * 2 * HID);
        float4* s4 = (float4*)&s_rep[0][0];
        for (int i = threadIdx.x; i < FB * (2 * HID) / 4; i += 256) s4[i] = g4[i];
    }
    __syncthreads();
    const float* W = (o < CDIM) ? (Wc + (size_t)o * 2 * HID)
                                : (Ws + (size_t)(o - CDIM) * 2 * HID);
    const float4* W4 = (const float4*)W;
    float acc[FB] = {};
#pragma unroll
    for (int t = 0; t < 12; t++) {
        float4 wv = W4[lane + 32 * t];
#pragma unroll
        for (int bb = 0; bb < FB; bb++) {
            float4 rv = *(const float4*)&s_rep[bb][4 * (lane + 32 * t)];
            acc[bb] += wv.x * rv.x + wv.y * rv.y + wv.z * rv.z + wv.w * rv.w;
        }
    }
#pragma unroll
    for (int off = 16; off; off >>= 1)
#pragma unroll
        for (int bb = 0; bb < FB; bb++)
            acc[bb] += __shfl_down_sync(0xffffffffu, acc[bb], off);
    if (lane == 0) {
        float gv = 1.f / (1.f + expf(-gate[0]));
        float bias = (o < CDIM) ? bc[o] : bs[o - CDIM];
        float sc = (o < CDIM) ? (1.f - gv) : gv;
#pragma unroll
        for (int bb = 0; bb < FB; bb++)
            g_fused[(b0 + bb) * NOUT + o] = (acc[bb] + bias) * sc;
    }
}

// ---------------- K_gram: symmetric 64x64 tiles -------------------------------
#define BT 64
#define BK 32
__global__ void __launch_bounds__(256) k_gram(const float* __restrict__ H) {
    const int TI[3] = {0, 0, 1};
    const int TJ[3] = {0, 1, 1};
    int b = blockIdx.y;
    int t = blockIdx.x;
    int ti = TI[t], tj = TJ[t];
    int i0 = ti * BT, j0 = tj * BT;
    int n = g_n0[b] + g_n1[b];
    if (i0 >= n || j0 >= n) return;
    __shared__ __align__(16) float sA[BK * (BT + 4)];
    __shared__ __align__(16) float sB[BK * (BT + 4)];
    int tid = threadIdx.x;            // 256
    int tx = tid & 15, ty = tid >> 4; // 16x16 threads, 4x4 each
    float acc[4][4] = {};
    const float* Hb = H + (size_t)b * LL * HID;
    int lr = tid >> 3;   // 0..31 (rows lr, lr+32)
    int lc = tid & 7;    // float4 column group
    for (int k0 = 0; k0 < HID; k0 += BK) {
#pragma unroll
        for (int h = 0; h < 2; h++) {
            int row = lr + 32 * h;
            float4 v = *(const float4*)(Hb + (size_t)(i0 + row) * HID + k0 + lc * 4);
            sA[(lc * 4 + 0) * (BT + 4) + row] = v.x;
            sA[(lc * 4 + 1) * (BT + 4) + row] = v.y;
            sA[(lc * 4 + 2) * (BT + 4) + row] = v.z;
            sA[(lc * 4 + 3) * (BT + 4) + row] = v.w;
            float4 u = *(const float4*)(Hb + (size_t)(j0 + row) * HID + k0 + lc * 4);
            sB[(lc * 4 + 0) * (BT + 4) + row] = u.x;
            sB[(lc * 4 + 1) * (BT + 4) + row] = u.y;
            sB[(lc * 4 + 2) * (BT + 4) + row] = u.z;
            sB[(lc * 4 + 3) * (BT + 4) + row] = u.w;
        }
        __syncthreads();
#pragma unroll
        for (int kk = 0; kk < BK; kk++) {
            float4 av = *(const float4*)&sA[kk * (BT + 4) + ty * 4];
            float4 bv = *(const float4*)&sB[kk * (BT + 4) + tx * 4];
            float ar[4] = {av.x, av.y, av.z, av.w};
            float br[4] = {bv.x, bv.y, bv.z, bv.w};
#pragma unroll
            for (int r = 0; r < 4; r++)
#pragma unroll
                for (int c = 0; c < 4; c++) acc[r][c] += ar[r] * br[c];
        }
        __syncthreads();
    }
    const float* sqb = g_sq + b * LL;
    float* out = g_Cs + (size_t)b * LL * LL;
#pragma unroll
    for (int r = 0; r < 4; r++) {
        int i = i0 + ty * 4 + r;
        float si = sqb[i];
#pragma unroll
        for (int c = 0; c < 4; c++) {
            int j = j0 + tx * 4 + c;
            float d2 = si + sqb[j] - 2.f * acc[r][c];
            float v = sqrtf(fmaxf(d2, 1e-6f)) * (L2E / EPSV);
            out[i * LL + j] = v;
            if (ti != tj) out[j * LL + i] = v;
        }
    }
}

// ---------------- K_sink: compact Sinkhorn ------------------------------------
__global__ void __launch_bounds__(128) k_sink() {
    extern __shared__ float cS[];
    __shared__ __align__(16) float s_u[128], s_w[128];
    __shared__ float s_red[4];
    int bx = blockIdx.x;
    int b = bx / 3, v = bx - 3 * b;
    int n0 = g_n0[b], n1 = g_n1[b];
    int ra, na, rb, nb;
    if (v == 0)      { ra = 0;  na = n0; rb = n0; nb = n1; }
    else if (v == 1) { ra = 0;  na = n0; rb = 0;  nb = n0; }
    else             { ra = n0; na = n1; rb = n0; nb = n1; }
    int tid = threadIdx.x;
    int nbp = (nb + 3) & ~3;
    int nap = (na + 3) & ~3;
    int pitch = nbp | 1;
    int tot = nap * pitch;
    for (int x = tid; x < tot; x += 128) cS[x] = INFN;
    __syncthreads();
    const float* src = g_Cs + (size_t)b * LL * LL;
    if (tid < nb) {
        for (int i = 0; i < na; i++)
            cS[i * pitch + tid] = src[(ra + i) * LL + rb + tid];
    }
    float la2 = -__log2f((float)na);
    float lb2 = -__log2f((float)nb);
    s_u[tid] = (tid < nb) ? lb2 : -INFN;
    s_w[tid] = -INFN;
    __syncthreads();
    float F = 0.f, G = 0.f;
    for (int it = 0; it < NIT; it++) {
        if (tid < na) {
            const float* cr = cS + tid * pitch;
            float m = -INFN;
            for (int j = 0; j < nbp; j += 4) {
                float4 u4 = *(const float4*)&s_u[j];
                float t0 = fmaxf(u4.x - cr[j],     u4.y - cr[j + 1]);
                float t1 = fmaxf(u4.z - cr[j + 2], u4.w - cr[j + 3]);
                m = fmaxf(m, fmaxf(t0, t1));
            }
            float s = 0.f;
            for (int j = 0; j < nbp; j += 4) {
                float4 u4 = *(const float4*)&s_u[j];
                s += exp2f(u4.x - cr[j] - m) + exp2f(u4.y - cr[j + 1] - m)
                   + exp2f(u4.z - cr[j + 2] - m) + exp2f(u4.w - cr[j + 3] - m);
            }
            F = -(m + __log2f(s));
        }
        __syncthreads();
        if (tid < na) s_w[tid] = la2 + F;
        __syncthreads();
        if (tid < nb) {
            float m = -INFN;
            for (int i = 0; i < nap; i += 4) {
                float4 w4 = *(const float4*)&s_w[i];
                const float* cc = cS + i * pitch + tid;
                float t0 = fmaxf(w4.x - cc[0],         w4.y - cc[pitch]);
                float t1 = fmaxf(w4.z - cc[2 * pitch], w4.w - cc[3 * pitch]);
                m = fmaxf(m, fmaxf(t0, t1));
            }
            float s = 0.f;
            for (int i = 0; i < nap; i += 4) {
                float4 w4 = *(const float4*)&s_w[i];
                const float* cc = cS + i * pitch + tid;
                s += exp2f(w4.x - cc[0] - m) + exp2f(w4.y - cc[pitch] - m)
                   + exp2f(w4.z - cc[2 * pitch] - m) + exp2f(w4.w - cc[3 * pitch] - m);
            }
            G = -(m + __log2f(s));
            s_u[tid] = lb2 + G;
        }
        __syncthreads();
    }
    float val = 0.f;
    if (tid < na) val += F * (1.f / (float)na);
    if (tid < nb) val += G * (1.f / (float)nb);
    val *= (EPSV / L2E);
#pragma unroll
    for (int o = 16; o; o >>= 1) val += __shfl_down_sync(0xffffffffu, val, o);
    if ((tid & 31) == 0) s_red[tid >> 5] = val;
    __syncthreads();
    if (tid == 0) g_sink[v * BB + b] = s_red[0] + s_red[1] + s_red[2] + s_red[3];
}

// ---------------- K_final ------------------------------------------------------
__global__ void k_final(const float* __restrict__ lnw, const float* __restrict__ lnb,
                        const float* __restrict__ Wcls, const float* __restrict__ bcls,
                        float* __restrict__ out) {
    int b = blockIdx.x, tid = threadIdx.x;  // 128
    __shared__ float s_feat[FEAT];
    __shared__ float s_r[8];
    for (int i = tid; i < FEAT; i += 128) {
        s_feat[i] = (i < NOUT)
            ? g_fused[b * NOUT + i]
            : (g_sink[b] - 0.5f * (g_sink[BB + b] + g_sink[2 * BB + b]));
    }
    __syncthreads();
    float s = 0.f, s2 = 0.f;
    for (int i = tid; i < FEAT; i += 128) {
        float x = s_feat[i];
        s += x; s2 += x * x;
    }
#pragma unroll
    for (int o = 16; o; o >>= 1) {
        s  += __shfl_down_sync(0xffffffffu, s, o);
        s2 += __shfl_down_sync(0xffffffffu, s2, o);
    }
    if ((tid & 31) == 0) { s_r[tid >> 5] = s; s_r[4 + (tid >> 5)] = s2; }
    __syncthreads();
    float S  = s_r[0] + s_r[1] + s_r[2] + s_r[3];
    float S2 = s_r[4] + s_r[5] + s_r[6] + s_r[7];
    float mu = S / (float)FEAT;
    float var = S2 / (float)FEAT - mu * mu;
    float rstd = rsqrtf(var + 1e-5f);
    float a0 = 0.f, a1 = 0.f;
    for (int i = tid; i < FEAT; i += 128) {
        float h = (s_feat[i] - mu) * rstd * lnw[i] + lnb[i];
        a0 += h * Wcls[i];
        a1 += h * Wcls[FEAT + i];
    }
#pragma unroll
    for (int o = 16; o; o >>= 1) {
        a0 += __shfl_down_sync(0xffffffffu, a0, o);
        a1 += __shfl_down_sync(0xffffffffu, a1, o);
    }
    __syncthreads();
    if ((tid & 31) == 0) { s_r[tid >> 5] = a0; s_r[4 + (tid >> 5)] = a1; }
    __syncthreads();
    if (tid == 0) {
        out[b * 2 + 0] = s_r[0] + s_r[1] + s_r[2] + s_r[3] + bcls[0];
        out[b * 2 + 1] = s_r[4] + s_r[5] + s_r[6] + s_r[7] + bcls[1];
    }
}

// ---------------- launch --------------------------------------------------------
#define SINK_SMEM (112 * 113 * 4)

extern "C" void kernel_launch(void* const* d_in, const int* in_sizes, int n_in,
                              void* d_out, int out_size) {
    const float* H    = (const float*)d_in[0];
    const int*   tt   = (const int*)d_in[1];
    const int*   am   = (const int*)d_in[2];
    const float* Wc   = (const float*)d_in[3];
    const float* bc   = (const float*)d_in[4];
    const float* Ws   = (const float*)d_in[5];
    const float* bs   = (const float*)d_in[6];
    const float* gate = (const float*)d_in[7];
    const float* lnw  = (const float*)d_in[8];
    const float* lnb  = (const float*)d_in[9];
    const float* Wcls = (const float*)d_in[10];
    const float* bcls = (const float*)d_in[11];
    float* out = (float*)d_out;

    cudaFuncSetAttribute(k_sink, cudaFuncAttributeMaxDynamicSharedMemorySize, SINK_SMEM);

    k_sq<<<(BB * LL) / 8, 256>>>(H);
    k_rep<<<dim3(BB, 6), 128>>>(H, tt, am);
    k_gram<<<dim3(3, BB), 256>>>(H);
    k_fused<<<dim3(40, BB / FB), 256>>>(Wc, bc, Ws, bs, gate);
    k_sink<<<3 * BB, 128, SINK_SMEM>>>();
    k_final<<<BB, 128>>>(lnw, lnb, Wcls, bcls, out);
}

// round 6
// speedup vs baseline: 1.0010x; 1.0010x over previous
#include <cuda_runtime.h>
#include <math.h>

#define BB 64
#define LL 128
#define HID 768
#define CDIM 256
#define SDIM 64
#define NOUT (CDIM + SDIM)      // 320
#define FEAT 321
#define NIT 30
#define EPSV 0.05f
#define L2E 1.4426950408889634f
#define INFN 3.0e38f

// ---------------- device scratch ---------------------------------------------
__device__ float g_Cs[BB * LL * LL];   // scaled cost (only [0,n)^2 valid)
__device__ float g_sq[BB * LL];
__device__ float g_rep[BB * 2 * HID];
__device__ float g_fused[BB * NOUT];
__device__ float g_sink[3 * BB];
__device__ int   g_n0[BB], g_n1[BB];
__device__ int   g_cnt[BB];

// ---------------- K_prep: counts + masked means + cls + row sq norms ---------
__global__ void __launch_bounds__(128) k_prep(
        const float* __restrict__ H, const int* __restrict__ tt,
        const int* __restrict__ am) {
    int b = blockIdx.x;
    int y = blockIdx.y;                    // 0..5
    int tid = threadIdx.x;                 // 128
    int d = y * 128 + tid;
    __shared__ float s_m0[LL], s_m1[LL];
    int a = am[b * LL + tid], t = tt[b * LL + tid];
    int f0 = (a == 1 && t == 0) ? 1 : 0;
    int f1 = (a == 1 && t == 1) ? 1 : 0;
    s_m0[tid] = (float)f0;
    s_m1[tid] = (float)f1;
    int n0 = __syncthreads_count(f0);
    int n1 = __syncthreads_count(f1);
    if (y == 0 && tid == 0) { g_n0[b] = n0; g_n1[b] = n1; g_cnt[b] = 0; }
    const float* Hb = H + (size_t)b * LL * HID;
    float a0 = 0.f, a1 = 0.f;
#pragma unroll 8
    for (int l = 0; l < LL; l++) {
        float h = Hb[l * HID + d];
        a0 += h * s_m0[l];
        a1 += h * s_m1[l];
    }
    float i0 = 1.f / fmaxf((float)n0, 1.f);
    float i1 = 1.f / fmaxf((float)n1, 1.f);
    g_rep[b * 2 * HID + d] = Hb[d];
    g_rep[b * 2 * HID + HID + d] = a0 * i0 - a1 * i1;
    // squared norms: block y, warp w handles rows y*4+w, step 24
    int w = tid >> 5, lane = tid & 31;
    for (int r = y * 4 + w; r < LL; r += 24) {
        const float4* p = (const float4*)(Hb + (size_t)r * HID);
        float s = 0.f;
#pragma unroll
        for (int tq = 0; tq < HID / 128; tq++) {
            float4 v = p[lane + 32 * tq];
            s += v.x * v.x + v.y * v.y + v.z * v.z + v.w * v.w;
        }
#pragma unroll
        for (int o = 16; o; o >>= 1) s += __shfl_down_sync(0xffffffffu, s, o);
        if (lane == 0) g_sq[b * LL + r] = s;
    }
}

// ---------------- K_fused: 8 outputs x 4 batches per block --------------------
#define FB 4
__global__ void __launch_bounds__(256) k_fused(
        const float* __restrict__ Wc, const float* __restrict__ bc,
        const float* __restrict__ Ws, const float* __restrict__ bs,
        const float* __restrict__ gate) {
    int b0 = blockIdx.y * FB;
    int w = threadIdx.x >> 5, lane = threadIdx.x & 31;
    int o = blockIdx.x * 8 + w;   // 0..319
    __shared__ __align__(16) float s_rep[FB][2 * HID];
    {
        const float4* g4 = (const float4*)(g_rep + (size_t)b0 * 2 * HID);
        float4* s4 = (float4*)&s_rep[0][0];
        for (int i = threadIdx.x; i < FB * (2 * HID) / 4; i += 256) s4[i] = g4[i];
    }
    __syncthreads();
    const float* W = (o < CDIM) ? (Wc + (size_t)o * 2 * HID)
                                : (Ws + (size_t)(o - CDIM) * 2 * HID);
    const float4* W4 = (const float4*)W;
    float acc[FB] = {};
#pragma unroll
    for (int t = 0; t < 12; t++) {
        float4 wv = W4[lane + 32 * t];
#pragma unroll
        for (int bb = 0; bb < FB; bb++) {
            float4 rv = *(const float4*)&s_rep[bb][4 * (lane + 32 * t)];
            acc[bb] += wv.x * rv.x + wv.y * rv.y + wv.z * rv.z + wv.w * rv.w;
        }
    }
#pragma unroll
    for (int off = 16; off; off >>= 1)
#pragma unroll
        for (int bb = 0; bb < FB; bb++)
            acc[bb] += __shfl_down_sync(0xffffffffu, acc[bb], off);
    if (lane == 0) {
        float gv = 1.f / (1.f + expf(-gate[0]));
        float bias = (o < CDIM) ? bc[o] : bs[o - CDIM];
        float sc = (o < CDIM) ? (1.f - gv) : gv;
#pragma unroll
        for (int bb = 0; bb < FB; bb++)
            g_fused[(b0 + bb) * NOUT + o] = (acc[bb] + bias) * sc;
    }
}

// ---------------- K_gram: symmetric 64x64 tiles -------------------------------
#define BT 64
#define BK 32
__global__ void __launch_bounds__(256) k_gram(const float* __restrict__ H) {
    const int TI[3] = {0, 0, 1};
    const int TJ[3] = {0, 1, 1};
    int b = blockIdx.y;
    int t = blockIdx.x;
    int ti = TI[t], tj = TJ[t];
    int i0 = ti * BT, j0 = tj * BT;
    int n = g_n0[b] + g_n1[b];
    if (i0 >= n || j0 >= n) return;
    __shared__ __align__(16) float sA[BK * (BT + 4)];
    __shared__ __align__(16) float sB[BK * (BT + 4)];
    int tid = threadIdx.x;            // 256
    int tx = tid & 15, ty = tid >> 4;
    float acc[4][4] = {};
    const float* Hb = H + (size_t)b * LL * HID;
    int lr = tid >> 3;
    int lc = tid & 7;
    for (int k0 = 0; k0 < HID; k0 += BK) {
#pragma unroll
        for (int h = 0; h < 2; h++) {
            int row = lr + 32 * h;
            float4 v = *(const float4*)(Hb + (size_t)(i0 + row) * HID + k0 + lc * 4);
            sA[(lc * 4 + 0) * (BT + 4) + row] = v.x;
            sA[(lc * 4 + 1) * (BT + 4) + row] = v.y;
            sA[(lc * 4 + 2) * (BT + 4) + row] = v.z;
            sA[(lc * 4 + 3) * (BT + 4) + row] = v.w;
            float4 u = *(const float4*)(Hb + (size_t)(j0 + row) * HID + k0 + lc * 4);
            sB[(lc * 4 + 0) * (BT + 4) + row] = u.x;
            sB[(lc * 4 + 1) * (BT + 4) + row] = u.y;
            sB[(lc * 4 + 2) * (BT + 4) + row] = u.z;
            sB[(lc * 4 + 3) * (BT + 4) + row] = u.w;
        }
        __syncthreads();
#pragma unroll
        for (int kk = 0; kk < BK; kk++) {
            float4 av = *(const float4*)&sA[kk * (BT + 4) + ty * 4];
            float4 bv = *(const float4*)&sB[kk * (BT + 4) + tx * 4];
            float ar[4] = {av.x, av.y, av.z, av.w};
            float br[4] = {bv.x, bv.y, bv.z, bv.w};
#pragma unroll
            for (int r = 0; r < 4; r++)
#pragma unroll
                for (int c = 0; c < 4; c++) acc[r][c] += ar[r] * br[c];
        }
        __syncthreads();
    }
    const float* sqb = g_sq + b * LL;
    float* out = g_Cs + (size_t)b * LL * LL;
#pragma unroll
    for (int r = 0; r < 4; r++) {
        int i = i0 + ty * 4 + r;
        float si = sqb[i];
#pragma unroll
        for (int c = 0; c < 4; c++) {
            int j = j0 + tx * 4 + c;
            float d2 = si + sqb[j] - 2.f * acc[r][c];
            float v = sqrtf(fmaxf(d2, 1e-6f)) * (L2E / EPSV);
            out[i * LL + j] = v;
            if (ti != tj) out[j * LL + i] = v;
        }
    }
}

// ---------------- K_sink: split-thread Sinkhorn + fused final ----------------
__global__ void __launch_bounds__(128) k_sink(
        const float* __restrict__ lnw, const float* __restrict__ lnb,
        const float* __restrict__ Wcls, const float* __restrict__ bcls,
        float* __restrict__ out) {
    extern __shared__ float cS[];
    __shared__ __align__(16) float s_u[128], s_w[128];
    __shared__ float s_red[8];
    __shared__ int s_last;
    int bx = blockIdx.x;
    int b = bx / 3, v = bx - 3 * b;
    int n0 = g_n0[b], n1 = g_n1[b];
    int ra, na, rb, nb;
    if (v == 0)      { ra = 0;  na = n0; rb = n0; nb = n1; }
    else if (v == 1) { ra = 0;  na = n0; rb = 0;  nb = n0; }
    else             { ra = n0; na = n1; rb = n0; nb = n1; }
    int tid = threadIdx.x;
    int nbp = (nb + 3) & ~3;
    int nap = (na + 3) & ~3;
    int pitch = nbp | 1;
    int sa = (na <= 32) ? 4 : (na <= 64) ? 2 : 1;   // threads per row
    int sb = (nb <= 32) ? 4 : (nb <= 64) ? 2 : 1;   // threads per col
    int rowi = tid / sa, rpart = tid % sa;
    int coli = tid / sb, cpart = tid % sb;
    // init + gather compact cost block
    int tot = nap * pitch;
    for (int x = tid; x < tot; x += 128) cS[x] = INFN;
    __syncthreads();
    const float* src = g_Cs + (size_t)b * LL * LL;
    if (tid < nb) {
        for (int i = 0; i < na; i++)
            cS[i * pitch + tid] = src[(ra + i) * LL + rb + tid];
    }
    float la2 = -__log2f((float)na);
    float lb2 = -__log2f((float)nb);
    s_u[tid] = (tid < nb) ? lb2 : -INFN;
    s_w[tid] = -INFN;
    __syncthreads();
    for (int it = 0; it < NIT; it++) {
        // ---- row pass: F over cols ----
        {
            float m = -INFN, ssum = 0.f;
            if (rowi < na) {
                const float* cr = cS + rowi * pitch;
                for (int j = rpart * 4; j < nbp; j += 4 * sa) {
                    float4 u4 = *(const float4*)&s_u[j];
                    float t0 = fmaxf(u4.x - cr[j],     u4.y - cr[j + 1]);
                    float t1 = fmaxf(u4.z - cr[j + 2], u4.w - cr[j + 3]);
                    m = fmaxf(m, fmaxf(t0, t1));
                }
                for (int j = rpart * 4; j < nbp; j += 4 * sa) {
                    float4 u4 = *(const float4*)&s_u[j];
                    ssum += exp2f(u4.x - cr[j] - m) + exp2f(u4.y - cr[j + 1] - m)
                          + exp2f(u4.z - cr[j + 2] - m) + exp2f(u4.w - cr[j + 3] - m);
                }
            }
#pragma unroll
            for (int o = 1; o < 4; o <<= 1) {
                if (o < sa) {
                    float om = __shfl_xor_sync(0xffffffffu, m, o);
                    float os = __shfl_xor_sync(0xffffffffu, ssum, o);
                    float nm = fmaxf(m, om);
                    ssum = ssum * exp2f(m - nm) + os * exp2f(om - nm);
                    m = nm;
                }
            }
            __syncthreads();
            if (rowi < na && rpart == 0)
                s_w[rowi] = la2 - (m + __log2f(ssum));
            __syncthreads();
        }
        // ---- col pass: G over rows ----
        {
            float m = -INFN, ssum = 0.f;
            if (coli < nb) {
                const float* cc = cS + coli;
                for (int i = cpart * 4; i < nap; i += 4 * sb) {
                    float4 w4 = *(const float4*)&s_w[i];
                    float t0 = fmaxf(w4.x - cc[i * pitch],       w4.y - cc[(i + 1) * pitch]);
                    float t1 = fmaxf(w4.z - cc[(i + 2) * pitch], w4.w - cc[(i + 3) * pitch]);
                    m = fmaxf(m, fmaxf(t0, t1));
                }
                for (int i = cpart * 4; i < nap; i += 4 * sb) {
                    float4 w4 = *(const float4*)&s_w[i];
                    ssum += exp2f(w4.x - cc[i * pitch] - m)       + exp2f(w4.y - cc[(i + 1) * pitch] - m)
                          + exp2f(w4.z - cc[(i + 2) * pitch] - m) + exp2f(w4.w - cc[(i + 3) * pitch] - m);
                }
            }
#pragma unroll
            for (int o = 1; o < 4; o <<= 1) {
                if (o < sb) {
                    float om = __shfl_xor_sync(0xffffffffu, m, o);
                    float os = __shfl_xor_sync(0xffffffffu, ssum, o);
                    float nm = fmaxf(m, om);
                    ssum = ssum * exp2f(m - nm) + os * exp2f(om - nm);
                    m = nm;
                }
            }
            __syncthreads();
            if (coli < nb && cpart == 0)
                s_u[coli] = lb2 - (m + __log2f(ssum));
            __syncthreads();
        }
    }
    // value: <a,f> + <b,g> ; F = s_w - la2, G = s_u - lb2
    float val = 0.f;
    if (tid < na) val += (s_w[tid] - la2) * (1.f / (float)na);
    if (tid < nb) val += (s_u[tid] - lb2) * (1.f / (float)nb);
    val *= (EPSV / L2E);
#pragma unroll
    for (int o = 16; o; o >>= 1) val += __shfl_down_sync(0xffffffffu, val, o);
    if ((tid & 31) == 0) s_red[tid >> 5] = val;
    __syncthreads();
    if (tid == 0) {
        g_sink[v * BB + b] = s_red[0] + s_red[1] + s_red[2] + s_red[3];
        __threadfence();
        int old = atomicAdd(&g_cnt[b], 1);
        s_last = (old == 2) ? 1 : 0;
    }
    __syncthreads();
    if (!s_last) return;
    __threadfence();
    // ---- fused final head for batch b ----
    __shared__ float s_feat[FEAT];
    float dot = g_sink[b] - 0.5f * (g_sink[BB + b] + g_sink[2 * BB + b]);
    for (int i = tid; i < FEAT; i += 128)
        s_feat[i] = (i < NOUT) ? g_fused[b * NOUT + i] : dot;
    __syncthreads();
    float s = 0.f, s2 = 0.f;
    for (int i = tid; i < FEAT; i += 128) {
        float x = s_feat[i];
        s += x; s2 += x * x;
    }
#pragma unroll
    for (int o = 16; o; o >>= 1) {
        s  += __shfl_down_sync(0xffffffffu, s, o);
        s2 += __shfl_down_sync(0xffffffffu, s2, o);
    }
    if ((tid & 31) == 0) { s_red[tid >> 5] = s; s_red[4 + (tid >> 5)] = s2; }
    __syncthreads();
    float S  = s_red[0] + s_red[1] + s_red[2] + s_red[3];
    float S2 = s_red[4] + s_red[5] + s_red[6] + s_red[7];
    float mu = S / (float)FEAT;
    float var = S2 / (float)FEAT - mu * mu;
    float rstd = rsqrtf(var + 1e-5f);
    float a0 = 0.f, a1 = 0.f;
    for (int i = tid; i < FEAT; i += 128) {
        float h = (s_feat[i] - mu) * rstd * lnw[i] + lnb[i];
        a0 += h * Wcls[i];
        a1 += h * Wcls[FEAT + i];
    }
#pragma unroll
    for (int o = 16; o; o >>= 1) {
        a0 += __shfl_down_sync(0xffffffffu, a0, o);
        a1 += __shfl_down_sync(0xffffffffu, a1, o);
    }
    __syncthreads();
    if ((tid & 31) == 0) { s_red[tid >> 5] = a0; s_red[4 + (tid >> 5)] = a1; }
    __syncthreads();
    if (tid == 0) {
        out[b * 2 + 0] = s_red[0] + s_red[1] + s_red[2] + s_red[3] + bcls[0];
        out[b * 2 + 1] = s_red[4] + s_red[5] + s_red[6] + s_red[7] + bcls[1];
    }
}

// ---------------- launch --------------------------------------------------------
#define SINK_SMEM (112 * 113 * 4)

extern "C" void kernel_launch(void* const* d_in, const int* in_sizes, int n_in,
                              void* d_out, int out_size) {
    const float* H    = (const float*)d_in[0];
    const int*   tt   = (const int*)d_in[1];
    const int*   am   = (const int*)d_in[2];
    const float* Wc   = (const float*)d_in[3];
    const float* bc   = (const float*)d_in[4];
    const float* Ws   = (const float*)d_in[5];
    const float* bs   = (const float*)d_in[6];
    const float* gate = (const float*)d_in[7];
    const float* lnw  = (const float*)d_in[8];
    const float* lnb  = (const float*)d_in[9];
    const float* Wcls = (const float*)d_in[10];
    const float* bcls = (const float*)d_in[11];
    float* out = (float*)d_out;

    cudaFuncSetAttribute(k_sink, cudaFuncAttributeMaxDynamicSharedMemorySize, SINK_SMEM);

    k_prep<<<dim3(BB, 6), 128>>>(H, tt, am);
    k_gram<<<dim3(3, BB), 256>>>(H);
    k_fused<<<dim3(40, BB / FB), 256>>>(Wc, bc, Ws, bs, gate);
    k_sink<<<3 * BB, 128, SINK_SMEM>>>(lnw, lnb, Wcls, bcls, out);
}

// round 7
// speedup vs baseline: 1.2201x; 1.2189x over previous
#include <cuda_runtime.h>
#include <math.h>

#define BB 64
#define LL 128
#define HID 768
#define CDIM 256
#define SDIM 64
#define NOUT (CDIM + SDIM)      // 320
#define FEAT 321
#define NIT 30
#define EPSV 0.05f
#define L2E 1.4426950408889634f
#define INFN 3.0e38f

__device__ __forceinline__ float ex2a(float x) {
    float y; asm("ex2.approx.f32 %0, %1;" : "=f"(y) : "f"(x)); return y;
}
__device__ __forceinline__ float lg2a(float x) {
    float y; asm("lg2.approx.f32 %0, %1;" : "=f"(y) : "f"(x)); return y;
}

// ---------------- device scratch ---------------------------------------------
__device__ float g_Cs[BB * LL * LL];   // scaled cost (only [0,n)^2 valid)
__device__ float g_sq[BB * LL];
__device__ float g_rep[BB * 2 * HID];
__device__ float g_fused[BB * NOUT];
__device__ float g_sink[3 * BB];
__device__ int   g_n0[BB], g_n1[BB];
__device__ int   g_cnt[BB];

// ---------------- K_prep: counts + masked means + cls + row sq norms ---------
__global__ void __launch_bounds__(128) k_prep(
        const float* __restrict__ H, const int* __restrict__ tt,
        const int* __restrict__ am) {
    int b = blockIdx.x;
    int y = blockIdx.y;                    // 0..5
    int tid = threadIdx.x;                 // 128
    int d = y * 128 + tid;
    __shared__ float s_m0[LL], s_m1[LL];
    int a = am[b * LL + tid], t = tt[b * LL + tid];
    int f0 = (a == 1 && t == 0) ? 1 : 0;
    int f1 = (a == 1 && t == 1) ? 1 : 0;
    s_m0[tid] = (float)f0;
    s_m1[tid] = (float)f1;
    int n0 = __syncthreads_count(f0);
    int n1 = __syncthreads_count(f1);
    if (y == 0 && tid == 0) { g_n0[b] = n0; g_n1[b] = n1; g_cnt[b] = 0; }
    const float* Hb = H + (size_t)b * LL * HID;
    float a0 = 0.f, a1 = 0.f;
#pragma unroll 8
    for (int l = 0; l < LL; l++) {
        float h = Hb[l * HID + d];
        a0 += h * s_m0[l];
        a1 += h * s_m1[l];
    }
    float i0 = 1.f / fmaxf((float)n0, 1.f);
    float i1 = 1.f / fmaxf((float)n1, 1.f);
    g_rep[b * 2 * HID + d] = Hb[d];
    g_rep[b * 2 * HID + HID + d] = a0 * i0 - a1 * i1;
    int w = tid >> 5, lane = tid & 31;
    for (int r = y * 4 + w; r < LL; r += 24) {
        const float4* p = (const float4*)(Hb + (size_t)r * HID);
        float s = 0.f;
#pragma unroll
        for (int tq = 0; tq < HID / 128; tq++) {
            float4 v = p[lane + 32 * tq];
            s += v.x * v.x + v.y * v.y + v.z * v.z + v.w * v.w;
        }
#pragma unroll
        for (int o = 16; o; o >>= 1) s += __shfl_down_sync(0xffffffffu, s, o);
        if (lane == 0) g_sq[b * LL + r] = s;
    }
}

// ---------------- K_fused: 8 outputs x 4 batches per block --------------------
#define FB 4
__global__ void __launch_bounds__(256) k_fused(
        const float* __restrict__ Wc, const float* __restrict__ bc,
        const float* __restrict__ Ws, const float* __restrict__ bs,
        const float* __restrict__ gate) {
    int b0 = blockIdx.y * FB;
    int w = threadIdx.x >> 5, lane = threadIdx.x & 31;
    int o = blockIdx.x * 8 + w;   // 0..319
    __shared__ __align__(16) float s_rep[FB][2 * HID];
    {
        const float4* g4 = (const float4*)(g_rep + (size_t)b0 * 2 * HID);
        float4* s4 = (float4*)&s_rep[0][0];
        for (int i = threadIdx.x; i < FB * (2 * HID) / 4; i += 256) s4[i] = g4[i];
    }
    __syncthreads();
    const float* W = (o < CDIM) ? (Wc + (size_t)o * 2 * HID)
                                : (Ws + (size_t)(o - CDIM) * 2 * HID);
    const float4* W4 = (const float4*)W;
    float acc[FB] = {};
#pragma unroll
    for (int t = 0; t < 12; t++) {
        float4 wv = W4[lane + 32 * t];
#pragma unroll
        for (int bb = 0; bb < FB; bb++) {
            float4 rv = *(const float4*)&s_rep[bb][4 * (lane + 32 * t)];
            acc[bb] += wv.x * rv.x + wv.y * rv.y + wv.z * rv.z + wv.w * rv.w;
        }
    }
#pragma unroll
    for (int off = 16; off; off >>= 1)
#pragma unroll
        for (int bb = 0; bb < FB; bb++)
            acc[bb] += __shfl_down_sync(0xffffffffu, acc[bb], off);
    if (lane == 0) {
        float gv = 1.f / (1.f + expf(-gate[0]));
        float bias = (o < CDIM) ? bc[o] : bs[o - CDIM];
        float sc = (o < CDIM) ? (1.f - gv) : gv;
#pragma unroll
        for (int bb = 0; bb < FB; bb++)
            g_fused[(b0 + bb) * NOUT + o] = (acc[bb] + bias) * sc;
    }
}

// ---------------- K_gram: symmetric 64x64 tiles -------------------------------
#define BT 64
#define BK 32
__global__ void __launch_bounds__(256) k_gram(const float* __restrict__ H) {
    const int TI[3] = {0, 0, 1};
    const int TJ[3] = {0, 1, 1};
    int b = blockIdx.y;
    int t = blockIdx.x;
    int ti = TI[t], tj = TJ[t];
    int i0 = ti * BT, j0 = tj * BT;
    int n = g_n0[b] + g_n1[b];
    if (i0 >= n || j0 >= n) return;
    __shared__ __align__(16) float sA[BK * (BT + 4)];
    __shared__ __align__(16) float sB[BK * (BT + 4)];
    int tid = threadIdx.x;            // 256
    int tx = tid & 15, ty = tid >> 4;
    float acc[4][4] = {};
    const float* Hb = H + (size_t)b * LL * HID;
    int lr = tid >> 3;
    int lc = tid & 7;
    for (int k0 = 0; k0 < HID; k0 += BK) {
#pragma unroll
        for (int h = 0; h < 2; h++) {
            int row = lr + 32 * h;
            float4 v = *(const float4*)(Hb + (size_t)(i0 + row) * HID + k0 + lc * 4);
            sA[(lc * 4 + 0) * (BT + 4) + row] = v.x;
            sA[(lc * 4 + 1) * (BT + 4) + row] = v.y;
            sA[(lc * 4 + 2) * (BT + 4) + row] = v.z;
            sA[(lc * 4 + 3) * (BT + 4) + row] = v.w;
            float4 u = *(const float4*)(Hb + (size_t)(j0 + row) * HID + k0 + lc * 4);
            sB[(lc * 4 + 0) * (BT + 4) + row] = u.x;
            sB[(lc * 4 + 1) * (BT + 4) + row] = u.y;
            sB[(lc * 4 + 2) * (BT + 4) + row] = u.z;
            sB[(lc * 4 + 3) * (BT + 4) + row] = u.w;
        }
        __syncthreads();
#pragma unroll
        for (int kk = 0; kk < BK; kk++) {
            float4 av = *(const float4*)&sA[kk * (BT + 4) + ty * 4];
            float4 bv = *(const float4*)&sB[kk * (BT + 4) + tx * 4];
            float ar[4] = {av.x, av.y, av.z, av.w};
            float br[4] = {bv.x, bv.y, bv.z, bv.w};
#pragma unroll
            for (int r = 0; r < 4; r++)
#pragma unroll
                for (int c = 0; c < 4; c++) acc[r][c] += ar[r] * br[c];
        }
        __syncthreads();
    }
    const float* sqb = g_sq + b * LL;
    float* out = g_Cs + (size_t)b * LL * LL;
#pragma unroll
    for (int r = 0; r < 4; r++) {
        int i = i0 + ty * 4 + r;
        float si = sqb[i];
#pragma unroll
        for (int c = 0; c < 4; c++) {
            int j = j0 + tx * 4 + c;
            float d2 = si + sqb[j] - 2.f * acc[r][c];
            float v = sqrtf(fmaxf(d2, 1e-6f)) * (L2E / EPSV);
            out[i * LL + j] = v;
            if (ti != tj) out[j * LL + i] = v;
        }
    }
}

// ---------------- K_sink: all-row-pass Sinkhorn + fused final -----------------
// lse row pass: out[row] = coef - log2 sum_j 2^(u[j] - M[row][j])  (max-stabilized)
__device__ __forceinline__ void lse_pass(const float* __restrict__ M, int p4, int nr,
                                         const float* __restrict__ u,
                                         float* __restrict__ outv,
                                         float coef, int tid) {
    int sp = (nr <= 32) ? 4 : (nr <= 64) ? 2 : 1;
    int row = tid / sp, part = tid - row * sp;
    float m = -INFN, s = 0.f;
    if (row < nr) {
        const float4* r4 = (const float4*)M + (size_t)row * p4;
        const float4* u4 = (const float4*)u;
        float m0 = -INFN, m1 = -INFN;
        for (int j = part; j < p4; j += sp) {
            float4 c = r4[j], uu = u4[j];
            m0 = fmaxf(m0, fmaxf(uu.x - c.x, uu.y - c.y));
            m1 = fmaxf(m1, fmaxf(uu.z - c.z, uu.w - c.w));
        }
        m = fmaxf(m0, m1);
        float s0 = 0.f, s1 = 0.f;
        for (int j = part; j < p4; j += sp) {
            float4 c = r4[j], uu = u4[j];
            s0 += ex2a(uu.x - c.x - m) + ex2a(uu.y - c.y - m);
            s1 += ex2a(uu.z - c.z - m) + ex2a(uu.w - c.w - m);
        }
        s = s0 + s1;
    }
#pragma unroll
    for (int o = 1; o < 4; o <<= 1) {
        if (o < sp) {
            float om = __shfl_xor_sync(0xffffffffu, m, o);
            float os = __shfl_xor_sync(0xffffffffu, s, o);
            float nm = fmaxf(m, om);
            s = s * ex2a(m - nm) + os * ex2a(om - nm);
            m = nm;
        }
    }
    if (row < nr && part == 0) outv[row] = coef - (m + lg2a(s));
}

__global__ void __launch_bounds__(128) k_sink(
        const float* __restrict__ lnw, const float* __restrict__ lnb,
        const float* __restrict__ Wcls, const float* __restrict__ bcls,
        float* __restrict__ out) {
    extern __shared__ __align__(16) float sm[];
    __shared__ __align__(16) float s_u[128], s_w[128];
    __shared__ float s_red[8];
    __shared__ int s_last;
    int bx = blockIdx.x;
    int b = bx / 3, v = bx - 3 * b;
    int n0 = g_n0[b], n1 = g_n1[b];
    int ra, na, rb, nb;
    if (v == 0)      { ra = 0;  na = n0; rb = n0; nb = n1; }
    else if (v == 1) { ra = 0;  na = n0; rb = 0;  nb = n0; }
    else             { ra = n0; na = n1; rb = n0; nb = n1; }
    int tid = threadIdx.x;
    int pa4 = ((nb + 3) >> 2) | 1;        // float4 pitch of A (na x nb), odd
    int pt4 = ((na + 3) >> 2) | 1;        // float4 pitch of AT (nb x na), odd
    float* A = sm;
    float* T = (v == 0) ? (sm + na * pa4 * 4) : sm;   // symmetric: T == A
    int ptu4 = (v == 0) ? pt4 : pa4;
    // init padding to +INFN
    {
        int totA = na * pa4 * 4;
        int totT = (v == 0) ? nb * pt4 * 4 : 0;
        for (int x = tid; x < totA; x += 128) A[x] = INFN;
        for (int x = tid; x < totT; x += 128) T[x] = INFN;
    }
    __syncthreads();
    // gather compact cost block (and transpose for cross variant)
    const float* src = g_Cs + (size_t)b * LL * LL;
    if (tid < nb) {
        for (int i = 0; i < na; i++) {
            float cv = src[(ra + i) * LL + rb + tid];
            A[i * pa4 * 4 + tid] = cv;
            if (v == 0) T[tid * pt4 * 4 + i] = cv;
        }
    }
    float la2 = -lg2a((float)na);
    float lb2 = -lg2a((float)nb);
    s_u[tid] = (tid < nb) ? lb2 : -INFN;
    s_w[tid] = -INFN;
    __syncthreads();
    for (int it = 0; it < NIT; it++) {
        lse_pass(A, pa4, na, s_u, s_w, la2, tid);
        __syncthreads();
        lse_pass(T, ptu4, nb, s_w, s_u, lb2, tid);
        __syncthreads();
    }
    // value: <a,f> + <b,g>; f = eps/L2E*(w - la2), g = eps/L2E*(u - lb2)
    float val = 0.f;
    if (tid < na) val += (s_w[tid] - la2) * (1.f / (float)na);
    if (tid < nb) val += (s_u[tid] - lb2) * (1.f / (float)nb);
    val *= (EPSV / L2E);
#pragma unroll
    for (int o = 16; o; o >>= 1) val += __shfl_down_sync(0xffffffffu, val, o);
    if ((tid & 31) == 0) s_red[tid >> 5] = val;
    __syncthreads();
    if (tid == 0) {
        g_sink[v * BB + b] = s_red[0] + s_red[1] + s_red[2] + s_red[3];
        __threadfence();
        int old = atomicAdd(&g_cnt[b], 1);
        s_last = (old == 2) ? 1 : 0;
    }
    __syncthreads();
    if (!s_last) return;
    __threadfence();
    // ---- fused final head for batch b ----
    __shared__ float s_feat[FEAT];
    float dot = g_sink[b] - 0.5f * (g_sink[BB + b] + g_sink[2 * BB + b]);
    for (int i = tid; i < FEAT; i += 128)
        s_feat[i] = (i < NOUT) ? g_fused[b * NOUT + i] : dot;
    __syncthreads();
    float s = 0.f, s2 = 0.f;
    for (int i = tid; i < FEAT; i += 128) {
        float x = s_feat[i];
        s += x; s2 += x * x;
    }
#pragma unroll
    for (int o = 16; o; o >>= 1) {
        s  += __shfl_down_sync(0xffffffffu, s, o);
        s2 += __shfl_down_sync(0xffffffffu, s2, o);
    }
    if ((tid & 31) == 0) { s_red[tid >> 5] = s; s_red[4 + (tid >> 5)] = s2; }
    __syncthreads();
    float S  = s_red[0] + s_red[1] + s_red[2] + s_red[3];
    float S2 = s_red[4] + s_red[5] + s_red[6] + s_red[7];
    float mu = S / (float)FEAT;
    float var = S2 / (float)FEAT - mu * mu;
    float rstd = rsqrtf(var + 1e-5f);
    float a0 = 0.f, a1 = 0.f;
    for (int i = tid; i < FEAT; i += 128) {
        float h = (s_feat[i] - mu) * rstd * lnw[i] + lnb[i];
        a0 += h * Wcls[i];
        a1 += h * Wcls[FEAT + i];
    }
#pragma unroll
    for (int o = 16; o; o >>= 1) {
        a0 += __shfl_down_sync(0xffffffffu, a0, o);
        a1 += __shfl_down_sync(0xffffffffu, a1, o);
    }
    __syncthreads();
    if ((tid & 31) == 0) { s_red[tid >> 5] = a0; s_red[4 + (tid >> 5)] = a1; }
    __syncthreads();
    if (tid == 0) {
        out[b * 2 + 0] = s_red[0] + s_red[1] + s_red[2] + s_red[3] + bcls[0];
        out[b * 2 + 1] = s_red[4] + s_red[5] + s_red[6] + s_red[7] + bcls[1];
    }
}

// ---------------- launch --------------------------------------------------------
#define SINK_SMEM (112 * 116 * 4)   // worst case: v2 with n1=112, pitch4=29

extern "C" void kernel_launch(void* const* d_in, const int* in_sizes, int n_in,
                              void* d_out, int out_size) {
    const float* H    = (const float*)d_in[0];
    const int*   tt   = (const int*)d_in[1];
    const int*   am   = (const int*)d_in[2];
    const float* Wc   = (const float*)d_in[3];
    const float* bc   = (const float*)d_in[4];
    const float* Ws   = (const float*)d_in[5];
    const float* bs   = (const float*)d_in[6];
    const float* gate = (const float*)d_in[7];
    const float* lnw  = (const float*)d_in[8];
    const float* lnb  = (const float*)d_in[9];
    const float* Wcls = (const float*)d_in[10];
    const float* bcls = (const float*)d_in[11];
    float* out = (float*)d_out;

    cudaFuncSetAttribute(k_sink, cudaFuncAttributeMaxDynamicSharedMemorySize, SINK_SMEM);

    k_prep<<<dim3(BB, 6), 128>>>(H, tt, am);
    k_gram<<<dim3(3, BB), 256>>>(H);
    k_fused<<<dim3(40, BB / FB), 256>>>(Wc, bc, Ws, bs, gate);
    k_sink<<<3 * BB, 128, SINK_SMEM>>>(lnw, lnb, Wcls, bcls, out);
}

// round 8
// speedup vs baseline: 1.3395x; 1.0978x over previous
#include <cuda_runtime.h>
#include <math.h>

#define BB 64
#define LL 128
#define HID 768
#define CDIM 256
#define SDIM 64
#define NOUT (CDIM + SDIM)      // 320
#define FEAT 321
#define NIT 30
#define EPSV 0.05f
#define L2E 1.4426950408889634f
#define INFN 3.0e38f

__device__ __forceinline__ float ex2a(float x) {
    float y; asm("ex2.approx.f32 %0, %1;" : "=f"(y) : "f"(x)); return y;
}
__device__ __forceinline__ float lg2a(float x) {
    float y; asm("lg2.approx.f32 %0, %1;" : "=f"(y) : "f"(x)); return y;
}

// ---------------- device scratch ---------------------------------------------
__device__ float g_Cs[BB * LL * LL];   // scaled cost (only [0,n)^2 valid)
__device__ float g_sq[BB * LL];
__device__ float g_rep[BB * 2 * HID];
__device__ float g_fused[BB * NOUT];
__device__ float g_sink[3 * BB];
__device__ int   g_n0[BB], g_n1[BB];
__device__ int   g_cnt[BB];

// ---------------- K_prep: counts + masked means + cls + row sq norms ---------
__global__ void __launch_bounds__(128) k_prep(
        const float* __restrict__ H, const int* __restrict__ tt,
        const int* __restrict__ am) {
    int b = blockIdx.x;
    int y = blockIdx.y;                    // 0..5
    int tid = threadIdx.x;                 // 128
    int d = y * 128 + tid;
    __shared__ float s_m0[LL], s_m1[LL];
    int a = am[b * LL + tid], t = tt[b * LL + tid];
    int f0 = (a == 1 && t == 0) ? 1 : 0;
    int f1 = (a == 1 && t == 1) ? 1 : 0;
    s_m0[tid] = (float)f0;
    s_m1[tid] = (float)f1;
    int n0 = __syncthreads_count(f0);
    int n1 = __syncthreads_count(f1);
    if (y == 0 && tid == 0) { g_n0[b] = n0; g_n1[b] = n1; g_cnt[b] = 0; }
    const float* Hb = H + (size_t)b * LL * HID;
    float a0 = 0.f, a1 = 0.f;
#pragma unroll 8
    for (int l = 0; l < LL; l++) {
        float h = Hb[l * HID + d];
        a0 += h * s_m0[l];
        a1 += h * s_m1[l];
    }
    float i0 = 1.f / fmaxf((float)n0, 1.f);
    float i1 = 1.f / fmaxf((float)n1, 1.f);
    g_rep[b * 2 * HID + d] = Hb[d];
    g_rep[b * 2 * HID + HID + d] = a0 * i0 - a1 * i1;
    int w = tid >> 5, lane = tid & 31;
    for (int r = y * 4 + w; r < LL; r += 24) {
        const float4* p = (const float4*)(Hb + (size_t)r * HID);
        float s = 0.f;
#pragma unroll
        for (int tq = 0; tq < HID / 128; tq++) {
            float4 v = p[lane + 32 * tq];
            s += v.x * v.x + v.y * v.y + v.z * v.z + v.w * v.w;
        }
#pragma unroll
        for (int o = 16; o; o >>= 1) s += __shfl_down_sync(0xffffffffu, s, o);
        if (lane == 0) g_sq[b * LL + r] = s;
    }
}

// ---------------- K_fused: 8 outputs x 4 batches per block --------------------
#define FB 4
__global__ void __launch_bounds__(256) k_fused(
        const float* __restrict__ Wc, const float* __restrict__ bc,
        const float* __restrict__ Ws, const float* __restrict__ bs,
        const float* __restrict__ gate) {
    int b0 = blockIdx.y * FB;
    int w = threadIdx.x >> 5, lane = threadIdx.x & 31;
    int o = blockIdx.x * 8 + w;   // 0..319
    __shared__ __align__(16) float s_rep[FB][2 * HID];
    {
        const float4* g4 = (const float4*)(g_rep + (size_t)b0 * 2 * HID);
        float4* s4 = (float4*)&s_rep[0][0];
        for (int i = threadIdx.x; i < FB * (2 * HID) / 4; i += 256) s4[i] = g4[i];
    }
    __syncthreads();
    const float* W = (o < CDIM) ? (Wc + (size_t)o * 2 * HID)
                                : (Ws + (size_t)(o - CDIM) * 2 * HID);
    const float4* W4 = (const float4*)W;
    float acc[FB] = {};
#pragma unroll
    for (int t = 0; t < 12; t++) {
        float4 wv = W4[lane + 32 * t];
#pragma unroll
        for (int bb = 0; bb < FB; bb++) {
            float4 rv = *(const float4*)&s_rep[bb][4 * (lane + 32 * t)];
            acc[bb] += wv.x * rv.x + wv.y * rv.y + wv.z * rv.z + wv.w * rv.w;
        }
    }
#pragma unroll
    for (int off = 16; off; off >>= 1)
#pragma unroll
        for (int bb = 0; bb < FB; bb++)
            acc[bb] += __shfl_down_sync(0xffffffffu, acc[bb], off);
    if (lane == 0) {
        float gv = 1.f / (1.f + expf(-gate[0]));
        float bias = (o < CDIM) ? bc[o] : bs[o - CDIM];
        float sc = (o < CDIM) ? (1.f - gv) : gv;
#pragma unroll
        for (int bb = 0; bb < FB; bb++)
            g_fused[(b0 + bb) * NOUT + o] = (acc[bb] + bias) * sc;
    }
}

// ---------------- K_gram: symmetric 64x64 tiles -------------------------------
#define BT 64
#define BK 32
__global__ void __launch_bounds__(256) k_gram(const float* __restrict__ H) {
    const int TI[3] = {0, 0, 1};
    const int TJ[3] = {0, 1, 1};
    int b = blockIdx.y;
    int t = blockIdx.x;
    int ti = TI[t], tj = TJ[t];
    int i0 = ti * BT, j0 = tj * BT;
    int n = g_n0[b] + g_n1[b];
    if (i0 >= n || j0 >= n) return;
    __shared__ __align__(16) float sA[BK * (BT + 4)];
    __shared__ __align__(16) float sB[BK * (BT + 4)];
    int tid = threadIdx.x;            // 256
    int tx = tid & 15, ty = tid >> 4;
    float acc[4][4] = {};
    const float* Hb = H + (size_t)b * LL * HID;
    int lr = tid >> 3;
    int lc = tid & 7;
    for (int k0 = 0; k0 < HID; k0 += BK) {
#pragma unroll
        for (int h = 0; h < 2; h++) {
            int row = lr + 32 * h;
            float4 v = *(const float4*)(Hb + (size_t)(i0 + row) * HID + k0 + lc * 4);
            sA[(lc * 4 + 0) * (BT + 4) + row] = v.x;
            sA[(lc * 4 + 1) * (BT + 4) + row] = v.y;
            sA[(lc * 4 + 2) * (BT + 4) + row] = v.z;
            sA[(lc * 4 + 3) * (BT + 4) + row] = v.w;
            float4 u = *(const float4*)(Hb + (size_t)(j0 + row) * HID + k0 + lc * 4);
            sB[(lc * 4 + 0) * (BT + 4) + row] = u.x;
            sB[(lc * 4 + 1) * (BT + 4) + row] = u.y;
            sB[(lc * 4 + 2) * (BT + 4) + row] = u.z;
            sB[(lc * 4 + 3) * (BT + 4) + row] = u.w;
        }
        __syncthreads();
#pragma unroll
        for (int kk = 0; kk < BK; kk++) {
            float4 av = *(const float4*)&sA[kk * (BT + 4) + ty * 4];
            float4 bv = *(const float4*)&sB[kk * (BT + 4) + tx * 4];
            float ar[4] = {av.x, av.y, av.z, av.w};
            float br[4] = {bv.x, bv.y, bv.z, bv.w};
#pragma unroll
            for (int r = 0; r < 4; r++)
#pragma unroll
                for (int c = 0; c < 4; c++) acc[r][c] += ar[r] * br[c];
        }
        __syncthreads();
    }
    const float* sqb = g_sq + b * LL;
    float* out = g_Cs + (size_t)b * LL * LL;
#pragma unroll
    for (int r = 0; r < 4; r++) {
        int i = i0 + ty * 4 + r;
        float si = sqb[i];
#pragma unroll
        for (int c = 0; c < 4; c++) {
            int j = j0 + tx * 4 + c;
            float d2 = si + sqb[j] - 2.f * acc[r][c];
            float v = sqrtf(fmaxf(d2, 1e-6f)) * (L2E / EPSV);
            out[i * LL + j] = v;
            if (ti != tj) out[j * LL + i] = v;
        }
    }
}

// ---------------- K_sink: 256-thread all-row-pass Sinkhorn + fused final ------
__device__ __forceinline__ void lse_pass(const float* __restrict__ M, int p4, int nr,
                                         const float* __restrict__ u,
                                         float* __restrict__ outv,
                                         float coef, int tid) {
    int sp = (nr <= 32) ? 8 : (nr <= 64) ? 4 : 2;   // threads per row (256 thr)
    int row = tid / sp, part = tid - row * sp;
    float m = -INFN, s = 0.f;
    if (row < nr) {
        const float4* r4 = (const float4*)M + (size_t)row * p4;
        const float4* u4 = (const float4*)u;
        float m0 = -INFN, m1 = -INFN;
        for (int j = part; j < p4; j += sp) {
            float4 c = r4[j], uu = u4[j];
            m0 = fmaxf(m0, fmaxf(uu.x - c.x, uu.y - c.y));
            m1 = fmaxf(m1, fmaxf(uu.z - c.z, uu.w - c.w));
        }
        m = fmaxf(m0, m1);
        float s0 = 0.f, s1 = 0.f;
        for (int j = part; j < p4; j += sp) {
            float4 c = r4[j], uu = u4[j];
            s0 += ex2a(uu.x - c.x - m) + ex2a(uu.y - c.y - m);
            s1 += ex2a(uu.z - c.z - m) + ex2a(uu.w - c.w - m);
        }
        s = s0 + s1;
    }
#pragma unroll
    for (int o = 1; o < 8; o <<= 1) {
        if (o < sp) {
            float om = __shfl_xor_sync(0xffffffffu, m, o);
            float os = __shfl_xor_sync(0xffffffffu, s, o);
            float nm = fmaxf(m, om);
            s = s * ex2a(m - nm) + os * ex2a(om - nm);
            m = nm;
        }
    }
    if (row < nr && part == 0) outv[row] = coef - (m + lg2a(s));
}

__global__ void __launch_bounds__(256) k_sink(
        const float* __restrict__ lnw, const float* __restrict__ lnb,
        const float* __restrict__ Wcls, const float* __restrict__ bcls,
        float* __restrict__ out) {
    extern __shared__ __align__(16) float sm[];
    __shared__ __align__(16) float s_u[128], s_w[128];
    __shared__ float s_red[16];
    __shared__ int s_last;
    int bx = blockIdx.x;
    // wave order: v2 (largest) first, then v0, then v1
    int vg = bx / BB;                 // 0,1,2
    int b = bx - vg * BB;
    int v = (vg == 0) ? 2 : (vg == 1) ? 0 : 1;
    int n0 = g_n0[b], n1 = g_n1[b];
    int ra, na, rb, nb;
    if (v == 0)      { ra = 0;  na = n0; rb = n0; nb = n1; }
    else if (v == 1) { ra = 0;  na = n0; rb = 0;  nb = n0; }
    else             { ra = n0; na = n1; rb = n0; nb = n1; }
    int tid = threadIdx.x;           // 256
    int pa4 = ((nb + 3) >> 2) | 1;   // float4 pitch of A (na x nb), odd
    int pt4 = ((na + 3) >> 2) | 1;   // float4 pitch of AT (nb x na), odd
    float* A = sm;
    float* T = (v == 0) ? (sm + na * pa4 * 4) : sm;   // symmetric: T == A
    int ptu4 = (v == 0) ? pt4 : pa4;
    {
        int totA = na * pa4 * 4;
        int totT = (v == 0) ? nb * pt4 * 4 : 0;
        for (int x = tid; x < totA; x += 256) A[x] = INFN;
        for (int x = tid; x < totT; x += 256) T[x] = INFN;
    }
    __syncthreads();
    // gather compact cost block (and transpose for cross variant); 2 row-groups
    const float* src = g_Cs + (size_t)b * LL * LL;
    {
        int j = tid & 127, q = tid >> 7;   // q in {0,1}
        if (j < nb) {
            for (int i = q; i < na; i += 2) {
                float cv = src[(ra + i) * LL + rb + j];
                A[i * pa4 * 4 + j] = cv;
                if (v == 0) T[j * pt4 * 4 + i] = cv;
            }
        }
    }
    float la2 = -lg2a((float)na);
    float lb2 = -lg2a((float)nb);
    if (tid < 128) {
        s_u[tid] = (tid < nb) ? lb2 : -INFN;
        s_w[tid] = -INFN;
    }
    __syncthreads();
    for (int it = 0; it < NIT; it++) {
        lse_pass(A, pa4, na, s_u, s_w, la2, tid);
        __syncthreads();
        lse_pass(T, ptu4, nb, s_w, s_u, lb2, tid);
        __syncthreads();
    }
    float val = 0.f;
    if (tid < na) val += (s_w[tid] - la2) * (1.f / (float)na);
    if (tid < nb) val += (s_u[tid] - lb2) * (1.f / (float)nb);
    val *= (EPSV / L2E);
#pragma unroll
    for (int o = 16; o; o >>= 1) val += __shfl_down_sync(0xffffffffu, val, o);
    if ((tid & 31) == 0) s_red[tid >> 5] = val;
    __syncthreads();
    if (tid == 0) {
        float acc = 0.f;
#pragma unroll
        for (int i = 0; i < 8; i++) acc += s_red[i];
        g_sink[v * BB + b] = acc;
        __threadfence();
        int old = atomicAdd(&g_cnt[b], 1);
        s_last = (old == 2) ? 1 : 0;
    }
    __syncthreads();
    if (!s_last) return;
    __threadfence();
    // ---- fused final head for batch b ----
    __shared__ float s_feat[FEAT];
    float dot = g_sink[b] - 0.5f * (g_sink[BB + b] + g_sink[2 * BB + b]);
    for (int i = tid; i < FEAT; i += 256)
        s_feat[i] = (i < NOUT) ? g_fused[b * NOUT + i] : dot;
    __syncthreads();
    float s = 0.f, s2 = 0.f;
    for (int i = tid; i < FEAT; i += 256) {
        float x = s_feat[i];
        s += x; s2 += x * x;
    }
#pragma unroll
    for (int o = 16; o; o >>= 1) {
        s  += __shfl_down_sync(0xffffffffu, s, o);
        s2 += __shfl_down_sync(0xffffffffu, s2, o);
    }
    if ((tid & 31) == 0) { s_red[tid >> 5] = s; s_red[8 + (tid >> 5)] = s2; }
    __syncthreads();
    float S = 0.f, S2 = 0.f;
#pragma unroll
    for (int i = 0; i < 8; i++) { S += s_red[i]; S2 += s_red[8 + i]; }
    float mu = S / (float)FEAT;
    float var = S2 / (float)FEAT - mu * mu;
    float rstd = rsqrtf(var + 1e-5f);
    float a0 = 0.f, a1 = 0.f;
    for (int i = tid; i < FEAT; i += 256) {
        float h = (s_feat[i] - mu) * rstd * lnw[i] + lnb[i];
        a0 += h * Wcls[i];
        a1 += h * Wcls[FEAT + i];
    }
#pragma unroll
    for (int o = 16; o; o >>= 1) {
        a0 += __shfl_down_sync(0xffffffffu, a0, o);
        a1 += __shfl_down_sync(0xffffffffu, a1, o);
    }
    __syncthreads();
    if ((tid & 31) == 0) { s_red[tid >> 5] = a0; s_red[8 + (tid >> 5)] = a1; }
    __syncthreads();
    if (tid == 0) {
        float r0 = 0.f, r1 = 0.f;
#pragma unroll
        for (int i = 0; i < 8; i++) { r0 += s_red[i]; r1 += s_red[8 + i]; }
        out[b * 2 + 0] = r0 + bcls[0];
        out[b * 2 + 1] = r1 + bcls[1];
    }
}

// ---------------- launch --------------------------------------------------------
#define SINK_SMEM (112 * 116 * 4)   // worst case: v2 with n1=112, pitch4=29

extern "C" void kernel_launch(void* const* d_in, const int* in_sizes, int n_in,
                              void* d_out, int out_size) {
    const float* H    = (const float*)d_in[0];
    const int*   tt   = (const int*)d_in[1];
    const int*   am   = (const int*)d_in[2];
    const float* Wc   = (const float*)d_in[3];
    const float* bc   = (const float*)d_in[4];
    const float* Ws   = (const float*)d_in[5];
    const float* bs   = (const float*)d_in[6];
    const float* gate = (const float*)d_in[7];
    const float* lnw  = (const float*)d_in[8];
    const float* lnb  = (const float*)d_in[9];
    const float* Wcls = (const float*)d_in[10];
    const float* bcls = (const float*)d_in[11];
    float* out = (float*)d_out;

    cudaFuncSetAttribute(k_sink, cudaFuncAttributeMaxDynamicSharedMemorySize, SINK_SMEM);

    k_prep<<<dim3(BB, 6), 128>>>(H, tt, am);
    k_gram<<<dim3(3, BB), 256>>>(H);
    k_fused<<<dim3(40, BB / FB), 256>>>(Wc, bc, Ws, bs, gate);
    k_sink<<<3 * BB, 256, SINK_SMEM>>>(lnw, lnb, Wcls, bcls, out);
}